// round 16
// baseline (speedup 1.0000x reference)
#include <cuda_runtime.h>
#include <cuda_bf16.h>
#include <cstdint>

// Fixed shapes from setup_inputs
#define BB 8
#define KK 8
#define KH 4                  // channels per block (K split across 2 blocks)
#define HH 1024
#define WW 1024
#define CH 16                 // rows computed per block
#define NBY (HH / CH)         // 64
#define NBLOCKS (NBY * BB * 2)  // 1024
#define GAMMA_C 10.0f
#define EPS_SQRT_C 1e-24f

#define NSTG 5
#define SETF (5 * WW)                      // floats per row-set: I + 4 p rows
#define SET_BYTES (SETF * 4)               // 20480
#define DYN_SMEM (NSTG * SET_BYTES)        // 102400

typedef unsigned long long u64;

// ---- packed f32x2 helpers ----
__device__ __forceinline__ u64 pk2(float lo, float hi) {
    u64 r; asm("mov.b64 %0, {%1, %2};" : "=l"(r) : "f"(lo), "f"(hi)); return r;
}
__device__ __forceinline__ void upk2(u64 v, float& lo, float& hi) {
    asm("mov.b64 {%0, %1}, %2;" : "=f"(lo), "=f"(hi) : "l"(v));
}
__device__ __forceinline__ u64 add2(u64 a, u64 b) {
    u64 d; asm("add.rn.f32x2 %0, %1, %2;" : "=l"(d) : "l"(a), "l"(b)); return d;
}
__device__ __forceinline__ u64 mul2(u64 a, u64 b) {
    u64 d; asm("mul.rn.f32x2 %0, %1, %2;" : "=l"(d) : "l"(a), "l"(b)); return d;
}
__device__ __forceinline__ u64 fma2(u64 a, u64 b, u64 c) {
    u64 d; asm("fma.rn.f32x2 %0, %1, %2, %3;" : "=l"(d) : "l"(a), "l"(b), "l"(c)); return d;
}

// ---- mbarrier / bulk-copy helpers ----
__device__ __forceinline__ void mbar_init(uint32_t a, uint32_t cnt) {
    asm volatile("mbarrier.init.shared.b64 [%0], %1;" :: "r"(a), "r"(cnt) : "memory");
}
__device__ __forceinline__ void mbar_expect_tx(uint32_t a, uint32_t bytes) {
    asm volatile("mbarrier.arrive.expect_tx.shared.b64 _, [%0], %1;"
                 :: "r"(a), "r"(bytes) : "memory");
}
__device__ __forceinline__ void mbar_wait(uint32_t a, uint32_t parity) {
    asm volatile(
        "{\n\t.reg .pred P;\n\t"
        "WAIT_%=:\n\t"
        "mbarrier.try_wait.parity.acquire.cta.shared::cta.b64 P, [%0], %1, 0x989680;\n\t"
        "@P bra DONE_%=;\n\t"
        "bra WAIT_%=;\n\t"
        "DONE_%=:\n\t}"
        :: "r"(a), "r"(parity) : "memory");
}
__device__ __forceinline__ void bulk_cp(uint32_t dst, const void* src,
                                        uint32_t bytes, uint32_t mbar) {
    asm volatile(
        "cp.async.bulk.shared::cta.global.mbarrier::complete_tx::bytes "
        "[%0], [%1], %2, [%3];"
        :: "r"(dst), "l"(src), "r"(bytes), "r"(mbar) : "memory");
}

// Per-block partials: [y][b*16 + half*8 + q]; q<4: nom[kk=q], q>=4: den[kk=q-4]
__device__ float g_part[NBY * BB * 16];
__device__ unsigned int g_count = 0;   // zero-init; last block resets it

__global__ __launch_bounds__(256, 2) void clustering_fused_kernel(
    const float* __restrict__ img,      // (B,1,H,W)
    const float* __restrict__ spacing,  // (2,)
    const float* __restrict__ p,        // (B,K,H,W)
    float* __restrict__ out)
{
    extern __shared__ float sm[];                  // [NSTG][5][WW]
    __shared__ __align__(8) u64 mbar[NSTG];

    const int b    = blockIdx.z;
    const int half = blockIdx.x;
    const int h0   = blockIdx.y * CH;
    const int w0   = 4 * threadIdx.x;              // 256 threads cover W=1024
    const int idxR = (w0 + 4 < WW) ? (w0 + 4) : (WW - 1);

    const float sx = spacing[0];
    const float sy = spacing[1];
    const float smin   = fminf(sx, sy);
    const float gsmin  = GAMMA_C * smin;
    const float inv_sx = 1.0f / sx;
    const float inv_sy = 1.0f / sy;

    const u64 ISX2 = pk2(inv_sx, inv_sx);
    const u64 ISY2 = pk2(inv_sy, inv_sy);
    const u64 NEG1 = pk2(-1.0f, -1.0f);
    const u64 NEG2 = pk2(-2.0f, -2.0f);

    const float* __restrict__ Ib = img + (size_t)b * HH * WW;
    const float* __restrict__ pb = p + (size_t)b * KK * HH * WW
                                     + (size_t)half * KH * HH * WW;

    const uint32_t sm_base   = (uint32_t)__cvta_generic_to_shared(sm);
    const uint32_t mbar_base = (uint32_t)__cvta_generic_to_shared(&mbar[0]);

    if (threadIdx.x == 0) {
#pragma unroll
        for (int s = 0; s < NSTG; s++) mbar_init(mbar_base + 8 * s, 1);
    }
    __syncthreads();

    auto issue_set = [&](int stage, int j) {     // row-set j -> stage
        int h = h0 + j; if (h > HH - 1) h = HH - 1;
        const uint32_t mb  = mbar_base + 8 * stage;
        const uint32_t dst = sm_base + stage * SET_BYTES;
        const size_t   go  = (size_t)h * WW;
        mbar_expect_tx(mb, SET_BYTES);
        bulk_cp(dst, Ib + go, WW * 4, mb);
#pragma unroll
        for (int k = 0; k < KH; k++)
            bulk_cp(dst + (k + 1) * WW * 4, pb + (size_t)k * HH * WW + go, WW * 4, mb);
    };

    // ---- prime: fill all 5 stages with sets 0..4 ----
    if (threadIdx.x == 0) {
#pragma unroll
        for (int s = 0; s < NSTG; s++) issue_set(s, s);
    }

    u64 nom2[KH], den2[KH];
    const u64 Z = pk2(0.0f, 0.0f);
#pragma unroll
    for (int k = 0; k < KH; k++) { nom2[k] = Z; den2[k] = Z; }

    // ring cursors: set r -> stage r%NSTG, parity (r/NSTG)&1
    int stgA = 0, phA = 0;          // cursor for set r
    int stgB = 1, phB = 0;          // cursor for set r+1

#pragma unroll 1
    for (int r = 0; r < CH; r++) {
        mbar_wait(mbar_base + 8 * stgA, (uint32_t)phA);
        mbar_wait(mbar_base + 8 * stgB, (uint32_t)phB);

        const float* stA = sm + stgA * SETF;
        const float* stB = sm + stgB * SETF;

        // ---- edge weights from I rows in smem ----
        const float4 iC = *(const float4*)(stA + w0);
        const float4 iN = *(const float4*)(stB + w0);
        const float  iR = stA[idxR];

        u64 wE01, wE23, tE01, tE23;
        {
            const u64 ic01 = pk2(iC.x, iC.y), ic23 = pk2(iC.z, iC.w);
            const u64 in01 = pk2(iN.x, iN.y), in23 = pk2(iN.z, iN.w);
            const u64 ir01 = pk2(iC.y, iC.z), ir23 = pk2(iC.w, iR);

            const u64 ix01 = fma2(ic01, NEG1, in01);
            const u64 ix23 = fma2(ic23, NEG1, in23);
            const u64 iy01 = fma2(ic01, NEG1, ir01);
            const u64 iy23 = fma2(ic23, NEG1, ir23);

            const u64 gx01 = mul2(ix01, ISX2), gx23 = mul2(ix23, ISX2);
            const u64 gy01 = mul2(iy01, ISY2), gy23 = mul2(iy23, ISY2);
            const u64 gn01 = fma2(gy01, gy01, mul2(gx01, gx01));
            const u64 gn23 = fma2(gy23, gy23, mul2(gx23, gx23));

            float g0, g1, g2, g3;
            upk2(gn01, g0, g1); upk2(gn23, g2, g3);
            const float w0_ = 1.0f / fmaf(gsmin, sqrtf(fmaxf(g0, EPS_SQRT_C)), 1.0f);
            const float w1_ = 1.0f / fmaf(gsmin, sqrtf(fmaxf(g1, EPS_SQRT_C)), 1.0f);
            const float w2_ = 1.0f / fmaf(gsmin, sqrtf(fmaxf(g2, EPS_SQRT_C)), 1.0f);
            const float w3_ = 1.0f / fmaf(gsmin, sqrtf(fmaxf(g3, EPS_SQRT_C)), 1.0f);
            wE01 = pk2(w0_, w1_); wE23 = pk2(w2_, w3_);
            tE01 = pk2(fmaf(2.0f, w0_, 1.0f), fmaf(2.0f, w1_, 1.0f));
            tE23 = pk2(fmaf(2.0f, w2_, 1.0f), fmaf(2.0f, w3_, 1.0f));
        }

#pragma unroll
        for (int k = 0; k < KH; k++) {
            const float* rowC = stA + (k + 1) * WW;
            const float* rowN = stB + (k + 1) * WW;
            const float4 c4 = *(const float4*)(rowC + w0);
            const float4 n4 = *(const float4*)(rowN + w0);
            const float  pRk = rowC[idxR];

            const u64 pc01 = pk2(c4.x, c4.y), pc23 = pk2(c4.z, c4.w);
            const u64 pr01 = pk2(c4.y, c4.z), pr23 = pk2(c4.w, pRk);
            const u64 pn01 = pk2(n4.x, n4.y), pn23 = pk2(n4.z, n4.w);

            const u64 s01 = add2(pn01, pr01), s23 = add2(pn23, pr23);
            const u64 d01 = fma2(NEG2, pc01, s01), d23 = fma2(NEG2, pc23, s23);
            const u64 t01 = fma2(wE01, d01, pc01), t23 = fma2(wE23, d23, pc23);
            nom2[k] = fma2(pc01, t01, nom2[k]);
            nom2[k] = fma2(pc23, t23, nom2[k]);
            den2[k] = fma2(pc01, tE01, den2[k]);
            den2[k] = fma2(pc23, tE23, den2[k]);
        }

        // set r fully consumed -> its stage (== stgA) takes set r+NSTG
        __syncthreads();
        if (r + NSTG <= CH) {
            if (threadIdx.x == 0) issue_set(stgA, r + NSTG);
        }

        if (++stgA == NSTG) { stgA = 0; phA ^= 1; }
        if (++stgB == NSTG) { stgB = 0; phB ^= 1; }
    }

    // ---- horizontal add of packed accumulators ----
    float nom[KH], den[KH];
#pragma unroll
    for (int k = 0; k < KH; k++) {
        float a, b2;
        upk2(nom2[k], a, b2); nom[k] = a + b2;
        upk2(den2[k], a, b2); den[k] = a + b2;
    }

    // ---- Block reduction of the 8 quantities ----
    __shared__ float sred[8][8];
    const int lane = threadIdx.x & 31;
    const int warp = threadIdx.x >> 5;

#pragma unroll
    for (int q = 0; q < 8; q++) {
        float v = (q < 4) ? nom[q] : den[q - 4];
#pragma unroll
        for (int off = 16; off > 0; off >>= 1)
            v += __shfl_xor_sync(0xFFFFFFFFu, v, off);
        if (lane == 0) sred[warp][q] = v;
    }
    __syncthreads();

    if (threadIdx.x < 8) {
        const int q = threadIdx.x;
        float v = 0.0f;
#pragma unroll
        for (int wp = 0; wp < 8; wp++) v += sred[wp][q];
        g_part[(size_t)blockIdx.y * (BB * 16) + b * 16 + half * 8 + q] = v;
    }

    // ---- Last-block finalize (ticket pattern; counter self-resets) ----
    __shared__ bool s_last;
    __threadfence();
    __syncthreads();
    if (threadIdx.x == 0) {
        unsigned int ticket = atomicAdd(&g_count, 1u);
        s_last = (ticket == NBLOCKS - 1);
    }
    __syncthreads();

    if (s_last) {
        __shared__ float s[256];
        __shared__ float c[BB * KK];
        const int t = threadIdx.x;
        const int q  = t & 127;
        const int hy = t >> 7;

        float v = 0.0f;
#pragma unroll 8
        for (int y = hy * (NBY / 2); y < (hy + 1) * (NBY / 2); y++)
            v += g_part[(size_t)y * (BB * 16) + q];
        s[t] = v;
        __syncthreads();

        if (t < BB * KK) {
            const int bb = t >> 3, k = t & 7;
            const int hf = k >> 2, kk = k & 3;
            const int cn = bb * 16 + hf * 8 + kk;
            const int cd = cn + 4;
            const float tn = s[cn] + s[128 + cn];
            const float td = s[cd] + s[128 + cd];
            c[t] = tn / td;                // cut_cost[b,k]
        }
        __syncthreads();

        if (t == 0) {
            float sum = 0.0f;
            for (int j = 0; j < BB * KK; j++) sum += c[j];
            out[0] = (float)(BB * KK) - sum;
            g_count = 0;                   // reset for next graph replay
        }
    }
}

extern "C" void kernel_launch(void* const* d_in, const int* in_sizes, int n_in,
                              void* d_out, int out_size) {
    const float* img     = (const float*)d_in[0];  // (8,1,1024,1024)
    const float* spacing = (const float*)d_in[1];  // (2,)
    const float* p       = (const float*)d_in[2];  // (8,8,1024,1024)
    float* out = (float*)d_out;

    cudaFuncSetAttribute(clustering_fused_kernel,
                         cudaFuncAttributeMaxDynamicSharedMemorySize, DYN_SMEM);

    dim3 grid(2, NBY, BB);   // (2, 64, 8) = 1024 blocks
    clustering_fused_kernel<<<grid, 256, DYN_SMEM>>>(img, spacing, p, out);
}

// round 17
// speedup vs baseline: 1.0318x; 1.0318x over previous
#include <cuda_runtime.h>
#include <cuda_bf16.h>
#include <cstdint>

// Fixed shapes from setup_inputs
#define BB 8
#define KK 8
#define KH 4                  // channels per block (K split across 2 blocks)
#define HH 1024
#define WW 1024
#define CH 8                  // rows computed per block
#define NBY (HH / CH)         // 128
#define NBLOCKS (NBY * BB * 2)  // 2048
#define GAMMA_C 10.0f
#define EPS_SQRT_C 1e-24f

#define NSTG 3
#define SETF (5 * WW)                      // floats per row-set: I + 4 p rows
#define SET_BYTES (SETF * 4)               // 20480
#define DYN_SMEM (NSTG * SET_BYTES)        // 61440

typedef unsigned long long u64;

// ---- packed f32x2 helpers ----
__device__ __forceinline__ u64 pk2(float lo, float hi) {
    u64 r; asm("mov.b64 %0, {%1, %2};" : "=l"(r) : "f"(lo), "f"(hi)); return r;
}
__device__ __forceinline__ void upk2(u64 v, float& lo, float& hi) {
    asm("mov.b64 {%0, %1}, %2;" : "=f"(lo), "=f"(hi) : "l"(v));
}
__device__ __forceinline__ u64 add2(u64 a, u64 b) {
    u64 d; asm("add.rn.f32x2 %0, %1, %2;" : "=l"(d) : "l"(a), "l"(b)); return d;
}
__device__ __forceinline__ u64 mul2(u64 a, u64 b) {
    u64 d; asm("mul.rn.f32x2 %0, %1, %2;" : "=l"(d) : "l"(a), "l"(b)); return d;
}
__device__ __forceinline__ u64 fma2(u64 a, u64 b, u64 c) {
    u64 d; asm("fma.rn.f32x2 %0, %1, %2, %3;" : "=l"(d) : "l"(a), "l"(b), "l"(c)); return d;
}

// ---- mbarrier / bulk-copy helpers ----
__device__ __forceinline__ void mbar_init(uint32_t a, uint32_t cnt) {
    asm volatile("mbarrier.init.shared.b64 [%0], %1;" :: "r"(a), "r"(cnt) : "memory");
}
__device__ __forceinline__ void mbar_expect_tx(uint32_t a, uint32_t bytes) {
    asm volatile("mbarrier.arrive.expect_tx.shared.b64 _, [%0], %1;"
                 :: "r"(a), "r"(bytes) : "memory");
}
__device__ __forceinline__ void mbar_arrive(uint32_t a) {
    asm volatile("mbarrier.arrive.release.cta.shared::cta.b64 _, [%0];"
                 :: "r"(a) : "memory");
}
__device__ __forceinline__ void mbar_wait(uint32_t a, uint32_t parity) {
    asm volatile(
        "{\n\t.reg .pred P;\n\t"
        "WAIT_%=:\n\t"
        "mbarrier.try_wait.parity.acquire.cta.shared::cta.b64 P, [%0], %1, 0x989680;\n\t"
        "@P bra DONE_%=;\n\t"
        "bra WAIT_%=;\n\t"
        "DONE_%=:\n\t}"
        :: "r"(a), "r"(parity) : "memory");
}
__device__ __forceinline__ void bulk_cp(uint32_t dst, const void* src,
                                        uint32_t bytes, uint32_t mbar) {
    asm volatile(
        "cp.async.bulk.shared::cta.global.mbarrier::complete_tx::bytes "
        "[%0], [%1], %2, [%3];"
        :: "r"(dst), "l"(src), "r"(bytes), "r"(mbar) : "memory");
}

// Per-block partials: [y][b*16 + half*8 + q]; q<4: nom[kk=q], q>=4: den[kk=q-4]
__device__ float g_part[NBY * BB * 16];
__device__ unsigned int g_count = 0;   // zero-init; last block resets it

__global__ __launch_bounds__(256, 3) void clustering_fused_kernel(
    const float* __restrict__ img,      // (B,1,H,W)
    const float* __restrict__ spacing,  // (2,)
    const float* __restrict__ p,        // (B,K,H,W)
    float* __restrict__ out)
{
    extern __shared__ float sm[];                  // [NSTG][5][WW]
    __shared__ __align__(8) u64 full_mb[NSTG];
    __shared__ __align__(8) u64 empty_mb[NSTG];

    const int b    = blockIdx.z;
    const int half = blockIdx.x;
    const int h0   = blockIdx.y * CH;
    const int w0   = 4 * threadIdx.x;              // 256 threads cover W=1024
    const int idxR = (w0 + 4 < WW) ? (w0 + 4) : (WW - 1);

    const float sx = spacing[0];
    const float sy = spacing[1];
    const float smin   = fminf(sx, sy);
    const float gsmin  = GAMMA_C * smin;
    const float inv_sx = 1.0f / sx;
    const float inv_sy = 1.0f / sy;

    const u64 ISX2 = pk2(inv_sx, inv_sx);
    const u64 ISY2 = pk2(inv_sy, inv_sy);
    const u64 NEG1 = pk2(-1.0f, -1.0f);
    const u64 NEG2 = pk2(-2.0f, -2.0f);

    const float* __restrict__ Ib = img + (size_t)b * HH * WW;
    const float* __restrict__ pb = p + (size_t)b * KK * HH * WW
                                     + (size_t)half * KH * HH * WW;

    const uint32_t sm_base  = (uint32_t)__cvta_generic_to_shared(sm);
    const uint32_t full_b   = (uint32_t)__cvta_generic_to_shared(&full_mb[0]);
    const uint32_t empty_b  = (uint32_t)__cvta_generic_to_shared(&empty_mb[0]);

    if (threadIdx.x == 0) {
#pragma unroll
        for (int s = 0; s < NSTG; s++) {
            mbar_init(full_b  + 8 * s, 1);
            mbar_init(empty_b + 8 * s, 256);
        }
    }
    __syncthreads();

    auto issue_set = [&](int stage, int j) {     // row-set j -> stage
        int h = h0 + j; if (h > HH - 1) h = HH - 1;
        const uint32_t mb  = full_b + 8 * stage;
        const uint32_t dst = sm_base + stage * SET_BYTES;
        const size_t   go  = (size_t)h * WW;
        mbar_expect_tx(mb, SET_BYTES);
        bulk_cp(dst, Ib + go, WW * 4, mb);
#pragma unroll
        for (int k = 0; k < KH; k++)
            bulk_cp(dst + (k + 1) * WW * 4, pb + (size_t)k * HH * WW + go, WW * 4, mb);
    };

    if (threadIdx.x == 0) {
        issue_set(0, 0);
        issue_set(1, 1);
        issue_set(2, 2);
    }

    u64 nom2[KH], den2[KH];
    const u64 Z = pk2(0.0f, 0.0f);
#pragma unroll
    for (int k = 0; k < KH; k++) { nom2[k] = Z; den2[k] = Z; }

#pragma unroll
    for (int r = 0; r < CH; r++) {
        const int sA = r % NSTG;              // current row-set r
        const int sB = (r + 1) % NSTG;        // next row-set r+1

        // sA's full barrier was already waited on last iteration (as sB);
        // only the first iteration needs it.
        if (r == 0) mbar_wait(full_b + 8 * sA, 0u);
        mbar_wait(full_b + 8 * sB, (uint32_t)(((r + 1) / NSTG) & 1));

        const float* stA = sm + sA * SETF;
        const float* stB = sm + sB * SETF;

        // ---- edge weights from I rows in smem ----
        const float4 iC = *(const float4*)(stA + w0);
        const float4 iN = *(const float4*)(stB + w0);
        const float  iR = stA[idxR];

        u64 wE01, wE23, tE01, tE23;
        {
            const u64 ic01 = pk2(iC.x, iC.y), ic23 = pk2(iC.z, iC.w);
            const u64 in01 = pk2(iN.x, iN.y), in23 = pk2(iN.z, iN.w);
            const u64 ir01 = pk2(iC.y, iC.z), ir23 = pk2(iC.w, iR);

            const u64 ix01 = fma2(ic01, NEG1, in01);
            const u64 ix23 = fma2(ic23, NEG1, in23);
            const u64 iy01 = fma2(ic01, NEG1, ir01);
            const u64 iy23 = fma2(ic23, NEG1, ir23);

            const u64 gx01 = mul2(ix01, ISX2), gx23 = mul2(ix23, ISX2);
            const u64 gy01 = mul2(iy01, ISY2), gy23 = mul2(iy23, ISY2);
            const u64 gn01 = fma2(gy01, gy01, mul2(gx01, gx01));
            const u64 gn23 = fma2(gy23, gy23, mul2(gx23, gx23));

            float g0, g1, g2, g3;
            upk2(gn01, g0, g1); upk2(gn23, g2, g3);
            const float w0_ = 1.0f / fmaf(gsmin, sqrtf(fmaxf(g0, EPS_SQRT_C)), 1.0f);
            const float w1_ = 1.0f / fmaf(gsmin, sqrtf(fmaxf(g1, EPS_SQRT_C)), 1.0f);
            const float w2_ = 1.0f / fmaf(gsmin, sqrtf(fmaxf(g2, EPS_SQRT_C)), 1.0f);
            const float w3_ = 1.0f / fmaf(gsmin, sqrtf(fmaxf(g3, EPS_SQRT_C)), 1.0f);
            wE01 = pk2(w0_, w1_); wE23 = pk2(w2_, w3_);
            tE01 = pk2(fmaf(2.0f, w0_, 1.0f), fmaf(2.0f, w1_, 1.0f));
            tE23 = pk2(fmaf(2.0f, w2_, 1.0f), fmaf(2.0f, w3_, 1.0f));
        }

#pragma unroll
        for (int k = 0; k < KH; k++) {
            const float* rowC = stA + (k + 1) * WW;
            const float* rowN = stB + (k + 1) * WW;
            const float4 c4 = *(const float4*)(rowC + w0);
            const float4 n4 = *(const float4*)(rowN + w0);
            const float  pRk = rowC[idxR];

            const u64 pc01 = pk2(c4.x, c4.y), pc23 = pk2(c4.z, c4.w);
            const u64 pr01 = pk2(c4.y, c4.z), pr23 = pk2(c4.w, pRk);
            const u64 pn01 = pk2(n4.x, n4.y), pn23 = pk2(n4.z, n4.w);

            const u64 s01 = add2(pn01, pr01), s23 = add2(pn23, pr23);
            const u64 d01 = fma2(NEG2, pc01, s01), d23 = fma2(NEG2, pc23, s23);
            const u64 t01 = fma2(wE01, d01, pc01), t23 = fma2(wE23, d23, pc23);
            nom2[k] = fma2(pc01, t01, nom2[k]);
            nom2[k] = fma2(pc23, t23, nom2[k]);
            den2[k] = fma2(pc01, tE01, den2[k]);
            den2[k] = fma2(pc23, tE23, den2[k]);
        }

        // Stage sA fully consumed by this thread (it was read as "next" last
        // iter and "current" now). Arrive and move on — no block-wide sync.
        mbar_arrive(empty_b + 8 * sA);

        if (r + NSTG <= CH) {
            if (threadIdx.x == 0) {
                mbar_wait(empty_b + 8 * sA, (uint32_t)((r / NSTG) & 1));
                issue_set(sA, r + NSTG);
            }
        }
    }

    // ---- horizontal add of packed accumulators ----
    float nom[KH], den[KH];
#pragma unroll
    for (int k = 0; k < KH; k++) {
        float a, b2;
        upk2(nom2[k], a, b2); nom[k] = a + b2;
        upk2(den2[k], a, b2); den[k] = a + b2;
    }

    // ---- Block reduction of the 8 quantities ----
    __shared__ float sred[8][8];
    const int lane = threadIdx.x & 31;
    const int warp = threadIdx.x >> 5;

#pragma unroll
    for (int q = 0; q < 8; q++) {
        float v = (q < 4) ? nom[q] : den[q - 4];
#pragma unroll
        for (int off = 16; off > 0; off >>= 1)
            v += __shfl_xor_sync(0xFFFFFFFFu, v, off);
        if (lane == 0) sred[warp][q] = v;
    }
    __syncthreads();

    if (threadIdx.x < 8) {
        const int q = threadIdx.x;
        float v = 0.0f;
#pragma unroll
        for (int wp = 0; wp < 8; wp++) v += sred[wp][q];
        g_part[(size_t)blockIdx.y * (BB * 16) + b * 16 + half * 8 + q] = v;
    }

    // ---- Last-block finalize (ticket pattern; counter self-resets) ----
    __shared__ bool s_last;
    __threadfence();
    __syncthreads();
    if (threadIdx.x == 0) {
        unsigned int ticket = atomicAdd(&g_count, 1u);
        s_last = (ticket == NBLOCKS - 1);
    }
    __syncthreads();

    if (s_last) {
        __shared__ float s[256];
        __shared__ float c[BB * KK];
        const int t = threadIdx.x;
        const int q  = t & 127;
        const int hy = t >> 7;

        float v = 0.0f;
#pragma unroll 8
        for (int y = hy * (NBY / 2); y < (hy + 1) * (NBY / 2); y++)
            v += g_part[(size_t)y * (BB * 16) + q];
        s[t] = v;
        __syncthreads();

        if (t < BB * KK) {
            const int bb = t >> 3, k = t & 7;
            const int hf = k >> 2, kk = k & 3;
            const int cn = bb * 16 + hf * 8 + kk;
            const int cd = cn + 4;
            const float tn = s[cn] + s[128 + cn];
            const float td = s[cd] + s[128 + cd];
            c[t] = tn / td;                // cut_cost[b,k]
        }
        __syncthreads();

        if (t == 0) {
            float sum = 0.0f;
            for (int j = 0; j < BB * KK; j++) sum += c[j];
            out[0] = (float)(BB * KK) - sum;
            g_count = 0;                   // reset for next graph replay
        }
    }
}

extern "C" void kernel_launch(void* const* d_in, const int* in_sizes, int n_in,
                              void* d_out, int out_size) {
    const float* img     = (const float*)d_in[0];  // (8,1,1024,1024)
    const float* spacing = (const float*)d_in[1];  // (2,)
    const float* p       = (const float*)d_in[2];  // (8,8,1024,1024)
    float* out = (float*)d_out;

    cudaFuncSetAttribute(clustering_fused_kernel,
                         cudaFuncAttributeMaxDynamicSharedMemorySize, DYN_SMEM);

    dim3 grid(2, NBY, BB);   // (2, 128, 8) = 2048 blocks
    clustering_fused_kernel<<<grid, 256, DYN_SMEM>>>(img, spacing, p, out);
}